// round 6
// baseline (speedup 1.0000x reference)
#include <cuda_runtime.h>

// deblurNet: out = x @ W.T with W complex DIAGONAL (inverse blur spectrum):
//   out[b,i] = (xr + j*xi)[b,i] * W[i,i]
//
// Round-5 post-mortem: ALL five faults are explained by the OUTPUT side:
// every round wrote 8 B/element interleaved complex64 (4.7 MB), but the
// harness's output dtype list has no complex type -- d_out is out_size
// 4-byte elements (likely f32 real part, 2.36 MB, or a 2*TOT f32 view of
// the complex array). Input reads were provably in-bounds in round 1 under
// reported element counts, so inputs are confirmed plain f32.
//
// This version never writes more than out_size*4 bytes:
//   out_size == 2*TOT -> interleaved re/im pairs (f32 view of complex64)
//   out_size ==   TOT -> real part only

#define TOT  589824   // B*N complex elements (64 * 9216)
#define NDIM 9216     // N = 96*96
#define DSTR 9217     // diagonal stride in dense [N,N] storage

// Each thread: 4 consecutive complex elements. mode: 0 = real-only, 1 = interleaved.
__global__ void deblur_diag_cmul(const float* __restrict__ xr,
                                 const float* __restrict__ xi,
                                 const float* __restrict__ wr,
                                 const float* __restrict__ wi,
                                 float* __restrict__ out,
                                 int mode) {
    int t = blockIdx.x * blockDim.x + threadIdx.x;
    int idx = t * 4;
    if (idx >= TOT) return;

    // NDIM % 4 == 0: a float4 never crosses a row boundary.
    const float4 ar = *reinterpret_cast<const float4*>(xr + idx);
    const float4 ai = *reinterpret_cast<const float4*>(xi + idx);

    const int i = idx % NDIM;
    const long long d0 = (long long)i * DSTR;  // max (NDIM-1)*DSTR = N^2-1
    const float w0r = __ldg(wr + d0),            w0i = __ldg(wi + d0);
    const float w1r = __ldg(wr + d0 + DSTR),     w1i = __ldg(wi + d0 + DSTR);
    const float w2r = __ldg(wr + d0 + 2 * DSTR), w2i = __ldg(wi + d0 + 2 * DSTR);
    const float w3r = __ldg(wr + d0 + 3 * DSTR), w3i = __ldg(wi + d0 + 3 * DSTR);

    const float o0r = fmaf(ar.x, w0r, -ai.x * w0i), o0i = fmaf(ar.x, w0i, ai.x * w0r);
    const float o1r = fmaf(ar.y, w1r, -ai.y * w1i), o1i = fmaf(ar.y, w1i, ai.y * w1r);
    const float o2r = fmaf(ar.z, w2r, -ai.z * w2i), o2i = fmaf(ar.z, w2i, ai.z * w2r);
    const float o3r = fmaf(ar.w, w3r, -ai.w * w3i), o3i = fmaf(ar.w, w3i, ai.w * w3r);

    if (mode == 1) {
        // Interleaved re/im (f32 view of complex64): 2*TOT floats total.
        float4* o = reinterpret_cast<float4*>(out) + (idx >> 1);  // 2 c64 per float4
        o[0] = make_float4(o0r, o0i, o1r, o1i);
        o[1] = make_float4(o2r, o2i, o3r, o3i);
    } else {
        // Real part only: TOT floats total.
        *reinterpret_cast<float4*>(out + idx) = make_float4(o0r, o1r, o2r, o3r);
    }
}

extern "C" void kernel_launch(void* const* d_in, const int* in_sizes, int n_in,
                              void* d_out, int out_size) {
    if (n_in < 4) return;

    // Robust classification (inputs confirmed f32, element counts): the pair
    // with the smaller size is x (B*N), the larger pair is W (N*N). Encounter
    // order within each pair is real-then-imag.
    long long smin = -1;
    for (int k = 0; k < 4; ++k) {
        long long s = (long long)in_sizes[k];
        if (smin < 0 || s < smin) smin = s;
    }
    const float* xs[2] = {nullptr, nullptr};
    const float* ws[2] = {nullptr, nullptr};
    int nx = 0, nw = 0;
    for (int k = 0; k < 4; ++k) {
        if ((long long)in_sizes[k] == smin && nx < 2) xs[nx++] = (const float*)d_in[k];
        else if (nw < 2)                              ws[nw++] = (const float*)d_in[k];
    }
    if (nx < 2 || nw < 2) return;

    // Output mode strictly bounded by out_size (4-byte elements).
    int mode;
    if ((long long)out_size >= 2LL * TOT) mode = 1;  // interleaved complex view
    else                                  mode = 0;  // real part only

    const int threads = 256;
    const int blocks = (TOT / 4 + threads - 1) / threads;  // 576
    deblur_diag_cmul<<<blocks, threads>>>(xs[0], xs[1], ws[0], ws[1],
                                          (float*)d_out, mode);
}

// round 7
// speedup vs baseline: 1.2738x; 1.2738x over previous
#include <cuda_runtime.h>

// deblurNet: out = x @ W.T with W complex DIAGONAL:
//   out[b,i] = (xr + j*xi)[b,i] * W[i,i]
//
// R6 profile: L1=45.5% / DRAM=7% / issue=4.7% -> L1-replay-bound on the
// stride-9217 diagonal gather (each gather LDG touches 32 distinct lines).
// Fix: kernel 1 compacts the N=9216 diagonal entries into a __device__
// float2 array ONCE (64x fewer scattered loads); kernel 2 is then a fully
// coalesced streaming complex multiply.

#define TOT  589824   // B*N complex elements (64 * 9216)
#define NDIM 9216     // N = 96*96
#define DSTR 9217     // diagonal stride in dense [N,N] f32 storage

__device__ float2 g_diag[NDIM];   // (wr[i,i], wi[i,i]) compacted

__global__ void gather_diag(const float* __restrict__ wr,
                            const float* __restrict__ wi) {
    int i = blockIdx.x * blockDim.x + threadIdx.x;
    if (i < NDIM) {
        long long d = (long long)i * DSTR;      // max N^2-1: in-bounds
        g_diag[i] = make_float2(__ldg(wr + d), __ldg(wi + d));
    }
}

// Each thread: 4 consecutive complex elements. mode: 0 = real-only, 1 = interleaved.
__global__ void deblur_diag_cmul(const float* __restrict__ xr,
                                 const float* __restrict__ xi,
                                 float* __restrict__ out,
                                 int mode) {
    int t = blockIdx.x * blockDim.x + threadIdx.x;
    int idx = t * 4;
    if (idx >= TOT) return;

    // NDIM % 4 == 0: float4 x-loads never cross a row boundary, and the
    // 4 diag entries are consecutive: two coalesced float4 loads.
    const float4 ar = *reinterpret_cast<const float4*>(xr + idx);
    const float4 ai = *reinterpret_cast<const float4*>(xi + idx);

    const int i = idx % NDIM;
    const float4 w01 = *reinterpret_cast<const float4*>(&g_diag[i]);     // w0r w0i w1r w1i
    const float4 w23 = *reinterpret_cast<const float4*>(&g_diag[i + 2]); // w2r w2i w3r w3i

    const float o0r = fmaf(ar.x, w01.x, -ai.x * w01.y), o0i = fmaf(ar.x, w01.y, ai.x * w01.x);
    const float o1r = fmaf(ar.y, w01.z, -ai.y * w01.w), o1i = fmaf(ar.y, w01.w, ai.y * w01.z);
    const float o2r = fmaf(ar.z, w23.x, -ai.z * w23.y), o2i = fmaf(ar.z, w23.y, ai.z * w23.x);
    const float o3r = fmaf(ar.w, w23.z, -ai.w * w23.w), o3i = fmaf(ar.w, w23.w, ai.w * w23.z);

    if (mode == 1) {
        // Interleaved re/im (f32 view of complex64): 2*TOT floats total.
        float4* o = reinterpret_cast<float4*>(out) + (idx >> 1);  // 2 c64 per float4
        o[0] = make_float4(o0r, o0i, o1r, o1i);
        o[1] = make_float4(o2r, o2i, o3r, o3i);
    } else {
        // Real part only: TOT floats total.
        *reinterpret_cast<float4*>(out + idx) = make_float4(o0r, o1r, o2r, o3r);
    }
}

extern "C" void kernel_launch(void* const* d_in, const int* in_sizes, int n_in,
                              void* d_out, int out_size) {
    if (n_in < 4) return;

    // Inputs are f32 at reported element counts (confirmed by R6 pass).
    // Smaller-size pair = x (B*N), larger pair = W (N*N); real before imag.
    long long smin = -1;
    for (int k = 0; k < 4; ++k) {
        long long s = (long long)in_sizes[k];
        if (smin < 0 || s < smin) smin = s;
    }
    const float* xs[2] = {nullptr, nullptr};
    const float* ws[2] = {nullptr, nullptr};
    int nx = 0, nw = 0;
    for (int k = 0; k < 4; ++k) {
        if ((long long)in_sizes[k] == smin && nx < 2) xs[nx++] = (const float*)d_in[k];
        else if (nw < 2)                              ws[nw++] = (const float*)d_in[k];
    }
    if (nx < 2 || nw < 2) return;

    // Output mode strictly bounded by out_size (4-byte elements).
    const int mode = ((long long)out_size >= 2LL * TOT) ? 1 : 0;

    gather_diag<<<(NDIM + 255) / 256, 256>>>(ws[0], ws[1]);

    const int threads = 256;
    const int blocks = (TOT / 4 + threads - 1) / threads;  // 576
    deblur_diag_cmul<<<blocks, threads>>>(xs[0], xs[1], (float*)d_out, mode);
}

// round 8
// speedup vs baseline: 1.5581x; 1.2233x over previous
#include <cuda_runtime.h>

// deblurNet: out = x @ W.T with W complex DIAGONAL:
//   out[b,i] = (xr + j*xi)[b,i] * W[i,i]
//
// R7 profile: nothing saturated (DRAM 11.5%, issue 11.6%) -> latency +
// two-launch overhead. This round: SINGLE fused kernel. Each thread owns
// 4 columns x 4 batches: gathers its 8 diagonal scalars straight from the
// dense W (scatter volume 16*9216*2 = 295K loads; distinct diag sectors
// ~590KB stay L2-resident), then streams 4 coalesced batch rows. 8 scatter
// + 8 float4 loads are independent -> MLP=16/thread hides DRAM latency.
// Grid = 144 blocks = one per SM, single wave, one launch.

#define TOT  589824   // B*N complex elements (64 * 9216)
#define NDIM 9216     // N = 96*96
#define DSTR 9217     // diagonal stride in dense [N,N] f32 storage
#define BATCH 64
#define CG   (NDIM / 4)     // 2304 column groups (4 cols = one float4)
#define BPT  4              // batches per thread
#define NBG  (BATCH / BPT)  // 16 batch groups

__global__ void __launch_bounds__(256)
deblur_fused(const float* __restrict__ xr,
             const float* __restrict__ xi,
             const float* __restrict__ wr,
             const float* __restrict__ wi,
             float* __restrict__ out,
             int mode) {
    const int gid = blockIdx.x * blockDim.x + threadIdx.x;   // 0 .. 36863
    const int colg = gid % CG;        // consecutive tids -> consecutive cols
    const int bg   = gid / CG;        // 0 .. 15
    const int i    = colg * 4;

    // Gather this thread's 4 diagonal entries (re+im = 8 scalars).
    // Max offset (NDIM-1)*DSTR = N^2-1: in-bounds. First batch group pulls
    // these sectors into L2; the other 15 groups hit.
    const long long d = (long long)i * DSTR;
    const float w0r = __ldg(wr + d),            w0i = __ldg(wi + d);
    const float w1r = __ldg(wr + d + DSTR),     w1i = __ldg(wi + d + DSTR);
    const float w2r = __ldg(wr + d + 2 * DSTR), w2i = __ldg(wi + d + 2 * DSTR);
    const float w3r = __ldg(wr + d + 3 * DSTR), w3i = __ldg(wi + d + 3 * DSTR);

    const int b0 = bg * BPT;
    #pragma unroll
    for (int bb = 0; bb < BPT; ++bb) {
        const int idx = (b0 + bb) * NDIM + i;    // max TOT-4: in-bounds
        const float4 ar = *reinterpret_cast<const float4*>(xr + idx);
        const float4 ai = *reinterpret_cast<const float4*>(xi + idx);

        const float o0r = fmaf(ar.x, w0r, -ai.x * w0i), o0i = fmaf(ar.x, w0i, ai.x * w0r);
        const float o1r = fmaf(ar.y, w1r, -ai.y * w1i), o1i = fmaf(ar.y, w1i, ai.y * w1r);
        const float o2r = fmaf(ar.z, w2r, -ai.z * w2i), o2i = fmaf(ar.z, w2i, ai.z * w2r);
        const float o3r = fmaf(ar.w, w3r, -ai.w * w3i), o3i = fmaf(ar.w, w3i, ai.w * w3r);

        if (mode == 1) {
            // Interleaved re/im (f32 view of complex64): 2*TOT floats.
            float4* o = reinterpret_cast<float4*>(out) + (idx >> 1);
            o[0] = make_float4(o0r, o0i, o1r, o1i);
            o[1] = make_float4(o2r, o2i, o3r, o3i);
        } else {
            // Real part only: TOT floats.
            *reinterpret_cast<float4*>(out + idx) = make_float4(o0r, o1r, o2r, o3r);
        }
    }
}

extern "C" void kernel_launch(void* const* d_in, const int* in_sizes, int n_in,
                              void* d_out, int out_size) {
    if (n_in < 4) return;

    // Inputs are f32 at reported element counts (confirmed R6/R7 passes).
    // Smaller-size pair = x (B*N), larger pair = W (N*N); real before imag.
    long long smin = -1;
    for (int k = 0; k < 4; ++k) {
        long long s = (long long)in_sizes[k];
        if (smin < 0 || s < smin) smin = s;
    }
    const float* xs[2] = {nullptr, nullptr};
    const float* ws[2] = {nullptr, nullptr};
    int nx = 0, nw = 0;
    for (int k = 0; k < 4; ++k) {
        if ((long long)in_sizes[k] == smin && nx < 2) xs[nx++] = (const float*)d_in[k];
        else if (nw < 2)                              ws[nw++] = (const float*)d_in[k];
    }
    if (nx < 2 || nw < 2) return;

    // Output mode strictly bounded by out_size (4-byte elements).
    const int mode = ((long long)out_size >= 2LL * TOT) ? 1 : 0;

    const int threads = 256;
    const int blocks = (CG * NBG) / threads;   // 36864 / 256 = 144
    deblur_fused<<<blocks, threads>>>(xs[0], xs[1], ws[0], ws[1],
                                      (float*)d_out, mode);
}

// round 9
// speedup vs baseline: 1.6106x; 1.0337x over previous
#include <cuda_runtime.h>

// deblurNet: out = x @ W.T with W complex DIAGONAL:
//   out[b,i] = (xr + j*xi)[b,i] * W[i,i]
//
// R8 profile: occ 12.3% / issue 1.2% (grid=144, 1 block/SM) -> latency-bound.
// This round: tiled fused kernel. Block = 64 cols x 16 batches, grid =
// 144*4 = 576 (4 blocks/SM, occ ~50%). Each block stages its 64 diagonal
// complex entries in smem (128 scattered loads/block, 74K chip-wide), then
// every thread does one fully-coalesced float4 column-group x batch.

#define TOT  589824   // B*N complex elements (64 * 9216)
#define NDIM 9216     // N = 96*96
#define DSTR 9217     // diagonal stride in dense [N,N] f32 storage
#define BATCH 64
#define TC   64               // columns per block tile
#define TB   16               // batches per block tile
#define NCT  (NDIM / TC)      // 144 column tiles
#define NBT  (BATCH / TB)     // 4 batch tiles

__global__ void __launch_bounds__(256)
deblur_tiled(const float* __restrict__ xr,
             const float* __restrict__ xi,
             const float* __restrict__ wr,
             const float* __restrict__ wi,
             float* __restrict__ out,
             int mode) {
    __shared__ float2 s_diag[TC];   // (wr[i,i], wi[i,i]) for this column tile

    const int ct = blockIdx.x % NCT;       // column tile
    const int bt = blockIdx.x / NCT;       // batch tile
    const int col0 = ct * TC;
    const int b0   = bt * TB;
    const int tid  = threadIdx.x;

    // Phase 1: stage the tile's diagonal. Max offset (NDIM-1)*DSTR = N^2-1.
    if (tid < TC) {
        const long long d = (long long)(col0 + tid) * DSTR;
        s_diag[tid] = make_float2(__ldg(wr + d), __ldg(wi + d));
    }
    __syncthreads();

    // Phase 2: one float4 column-group x one batch per thread.
    const int cg = tid & 15;          // 0..15 -> columns col0 + cg*4 .. +3
    const int b  = tid >> 4;          // 0..15 -> batch b0 + b
    const int i  = col0 + cg * 4;
    const int idx = (b0 + b) * NDIM + i;          // max TOT-4: in-bounds

    const float4 ar = *reinterpret_cast<const float4*>(xr + idx);
    const float4 ai = *reinterpret_cast<const float4*>(xi + idx);
    const float2 w0 = s_diag[cg * 4 + 0];
    const float2 w1 = s_diag[cg * 4 + 1];
    const float2 w2 = s_diag[cg * 4 + 2];
    const float2 w3 = s_diag[cg * 4 + 3];

    const float o0r = fmaf(ar.x, w0.x, -ai.x * w0.y), o0i = fmaf(ar.x, w0.y, ai.x * w0.x);
    const float o1r = fmaf(ar.y, w1.x, -ai.y * w1.y), o1i = fmaf(ar.y, w1.y, ai.y * w1.x);
    const float o2r = fmaf(ar.z, w2.x, -ai.z * w2.y), o2i = fmaf(ar.z, w2.y, ai.z * w2.x);
    const float o3r = fmaf(ar.w, w3.x, -ai.w * w3.y), o3i = fmaf(ar.w, w3.y, ai.w * w3.x);

    if (mode == 1) {
        // Interleaved re/im (f32 view of complex64): 2*TOT floats.
        float4* o = reinterpret_cast<float4*>(out) + (idx >> 1);
        o[0] = make_float4(o0r, o0i, o1r, o1i);
        o[1] = make_float4(o2r, o2i, o3r, o3i);
    } else {
        // Real part only: TOT floats.
        *reinterpret_cast<float4*>(out + idx) = make_float4(o0r, o1r, o2r, o3r);
    }
}

extern "C" void kernel_launch(void* const* d_in, const int* in_sizes, int n_in,
                              void* d_out, int out_size) {
    if (n_in < 4) return;

    // Inputs are f32 at reported element counts (confirmed R6-R8 passes).
    // Smaller-size pair = x (B*N), larger pair = W (N*N); real before imag.
    long long smin = -1;
    for (int k = 0; k < 4; ++k) {
        long long s = (long long)in_sizes[k];
        if (smin < 0 || s < smin) smin = s;
    }
    const float* xs[2] = {nullptr, nullptr};
    const float* ws[2] = {nullptr, nullptr};
    int nx = 0, nw = 0;
    for (int k = 0; k < 4; ++k) {
        if ((long long)in_sizes[k] == smin && nx < 2) xs[nx++] = (const float*)d_in[k];
        else if (nw < 2)                              ws[nw++] = (const float*)d_in[k];
    }
    if (nx < 2 || nw < 2) return;

    // Output mode strictly bounded by out_size (4-byte elements).
    const int mode = ((long long)out_size >= 2LL * TOT) ? 1 : 0;

    deblur_tiled<<<NCT * NBT, 256>>>(xs[0], xs[1], ws[0], ws[1],
                                     (float*)d_out, mode);   // 576 blocks
}